// round 13
// baseline (speedup 1.0000x reference)
#include <cuda_runtime.h>
#include <cstdint>

#define NTOK 8192
#define DIM 256
#define EDIM 16
#define NCODE 8192
#define CODES_PER_BLK 512          // 2 codes per lane, 64 per warp
#define NSPLIT (NCODE / CODES_PER_BLK)   // 16
#define TOKS_PER_DBLK 128          // token tile per dist block
#define LN_BLOCKS 512              // 16 tokens/block, warp-per-token
#define LG_BLOCKS 32               // 256 codes/block

typedef unsigned long long ull;

__device__ int g_count;                 // zero-init; reset by last dist block
__device__ int g_ticket;                // zero-init; reset by last dist block
__device__ float4 g_proj4[NTOK * 4];    // [slot][16] floats, PRE-SCALED by -2
__device__ float g_logits[NCODE];
__device__ float g_lse;
__device__ ull g_key[NTOK];

__device__ __forceinline__ ull pk2(float lo, float hi) {
    ull r;
    asm("mov.b64 %0, {%1, %2};" : "=l"(r) : "f"(lo), "f"(hi));
    return r;
}
__device__ __forceinline__ ull ffma2(ull a, ull b, ull c) {
    ull d;
    asm("fma.rn.f32x2 %0, %1, %2, %3;" : "=l"(d) : "l"(a), "l"(b), "l"(c));
    return d;
}
__device__ __forceinline__ float lo2(ull a) { return __uint_as_float((unsigned)a); }
__device__ __forceinline__ float hi2(ull a) { return __uint_as_float((unsigned)(a >> 32)); }

// embed 9-bit local code index into low mantissa bits (order perturbation <= 2^-14 rel)
__device__ __forceinline__ float embed_idx9(float d, unsigned idx) {
    return __uint_as_float((__float_as_uint(d) & 0xFFFFFE00u) | idx);
}

// ================= Kernel 1: block-specialized front =================
__global__ void __launch_bounds__(512) k_front(const float* __restrict__ xs,
                                               const void* __restrict__ pad,
                                               const void* __restrict__ mm,
                                               const float* __restrict__ gamma,
                                               const float* __restrict__ beta,
                                               const float* __restrict__ P,
                                               const float* __restrict__ W,
                                               const float* __restrict__ me) {
    int tid = threadIdx.x;
    int bx = blockIdx.x;

    if (bx >= LN_BLOCKS) {
        // ---- logits branch: 256 codes/block, 2 d-halves ----
        __shared__ float s_me[DIM];
        __shared__ float s_part[256];
        for (int i = tid; i < DIM; i += 512) s_me[i] = me[i];
        __syncthreads();
        int nl = tid & 255;
        int half = tid >> 8;
        int n = (bx - LN_BLOCKS) * 256 + nl;
        int d0 = half * 128;
        float a0 = 0.f, a1 = 0.f;
#pragma unroll 8
        for (int d = 0; d < 128; d += 2) {
            a0 = fmaf(s_me[d0 + d],     __ldg(&W[(size_t)(d0 + d)     * NCODE + n]), a0);
            a1 = fmaf(s_me[d0 + d + 1], __ldg(&W[(size_t)(d0 + d + 1) * NCODE + n]), a1);
        }
        float acc = a0 + a1;
        if (half == 1) s_part[nl] = acc;
        __syncthreads();
        if (half == 0) g_logits[n] = acc + s_part[nl];
        return;
    }

    // ---- LN + projection branch (warp per token, single pass) ----
    __shared__ __align__(16) ull s_P2[DIM * 9];   // gamma*P packed (e,e+1) f32x2, pitch 9 ull
    __shared__ float s_Pb[DIM * 17];              // beta*P, pitch 17
    __shared__ float s_redS[128], s_redC[128];
    __shared__ float s_S[16], s_c[16];
    __shared__ int   s_mm32[16], s_pd32[16];
    __shared__ unsigned s_mm8[4], s_pd8[4];
    __shared__ int   s_slot[16];

    int lane = tid & 31, wid = tid >> 5;

    int ni = 0, nf = 0;
    if (tid < 256) {
        int d = tid;
        float g = gamma[d], b = beta[d];
        float4 p0 = ((const float4*)P)[d * 4 + 0];
        float4 p1 = ((const float4*)P)[d * 4 + 1];
        float4 p2 = ((const float4*)P)[d * 4 + 2];
        float4 p3 = ((const float4*)P)[d * 4 + 3];
        ull* row = &s_P2[d * 9];
        row[0] = pk2(g * p0.x, g * p0.y); row[1] = pk2(g * p0.z, g * p0.w);
        row[2] = pk2(g * p1.x, g * p1.y); row[3] = pk2(g * p1.z, g * p1.w);
        row[4] = pk2(g * p2.x, g * p2.y); row[5] = pk2(g * p2.z, g * p2.w);
        row[6] = pk2(g * p3.x, g * p3.y); row[7] = pk2(g * p3.z, g * p3.w);
        float* rb = &s_Pb[d * 17];
        rb[0] = b * p0.x; rb[1] = b * p0.y; rb[2]  = b * p0.z; rb[3]  = b * p0.w;
        rb[4] = b * p1.x; rb[5] = b * p1.y; rb[6]  = b * p1.z; rb[7]  = b * p1.w;
        rb[8] = b * p2.x; rb[9] = b * p2.y; rb[10] = b * p2.z; rb[11] = b * p2.w;
        rb[12] = b * p3.x; rb[13] = b * p3.y; rb[14] = b * p3.z; rb[15] = b * p3.w;
    } else {
        int t = tid - 256;
        // mask dtype detection over first 2048 bytes of masked_masks (512 words)
        {
            unsigned v = ((const unsigned*)mm)[t + 256];
            if (v != 0u && v != 1u) ni = 1;
            if (v != 0u && v != 0x3f800000u) nf = 1;
        }
        // preload this block's mask words (both dtype interpretations)
        if (t < 16) s_mm32[t] = ((const int*)mm)[bx * 16 + t];
        else if (t < 32) s_pd32[t - 16] = ((const int*)pad)[bx * 16 + (t - 16)];
        else if (t < 36) s_mm8[t - 32] = ((const unsigned*)mm)[bx * 4 + (t - 32)];
        else if (t < 40) s_pd8[t - 36] = ((const unsigned*)pad)[bx * 4 + (t - 36)];
    }
    int bni = __syncthreads_or(ni);
    int bnf = __syncthreads_or(nf);
    int e4 = (!bni || !bnf) ? 1 : 0;

    // ---- phase 2: slots (warp 0) + S/c partial sums (tids 128..383) ----
    if (tid < 32) {
        bool m = false;
        if (tid < 16) {
            if (e4) m = (s_mm32[tid] != 0) && (s_pd32[tid] != 0);
            else {
                unsigned mb = (s_mm8[tid >> 2] >> ((tid & 3) * 8)) & 255u;
                unsigned pb = (s_pd8[tid >> 2] >> ((tid & 3) * 8)) & 255u;
                m = mb && pb;
            }
        }
        unsigned bal = __ballot_sync(0xffffffffu, m);
        int base = 0;
        if (tid == 0 && bal) base = atomicAdd(&g_count, __popc(bal));
        base = __shfl_sync(0xffffffffu, base, 0);
        if (tid < 16)
            s_slot[tid] = m ? (base + __popc(bal & ((1u << tid) - 1))) : -1;
    } else if (tid >= 128 && tid < 384) {
        int t = tid - 128;
        int e = t & 15, ch = (t >> 4) & 7;
        float s = 0.f;
        if (t < 128) {
            const float* pf = (const float*)s_P2;   // pitch 18 floats
#pragma unroll
            for (int i = 0; i < 32; i++) s += pf[(ch * 32 + i) * 18 + e];
            s_redS[ch * 16 + e] = s;
        } else {
#pragma unroll
            for (int i = 0; i < 32; i++) s += s_Pb[(ch * 32 + i) * 17 + e];
            s_redC[ch * 16 + e] = s;
        }
    }
    __syncthreads();
    if (tid < 16) {
        float v = 0.f;
#pragma unroll
        for (int c = 0; c < 8; c++) v += s_redS[c * 16 + tid];
        s_S[tid] = v;
    } else if (tid < 32) {
        int e = tid - 16;
        float v = 0.f;
#pragma unroll
        for (int c = 0; c < 8; c++) v += s_redC[c * 16 + e];
        s_c[e] = v;
    }
    __syncthreads();

    int slot = s_slot[wid];
    if (slot < 0) return;                 // whole warp exits (token unmasked)
    int tok = bx * 16 + wid;

    const float* xp = xs + (size_t)tok * DIM + lane;
    ull a2[8];
#pragma unroll
    for (int j = 0; j < 8; j++) a2[j] = 0ull;
    float sum = 0.f, sq = 0.f;
#pragma unroll
    for (int s = 0; s < 8; s++) {
        float xv = xp[32 * s];
        sum += xv; sq = fmaf(xv, xv, sq);
        ull x2 = pk2(xv, xv);
        const ull* pr = &s_P2[(lane + 32 * s) * 9];
#pragma unroll
        for (int j = 0; j < 8; j++) a2[j] = ffma2(x2, pr[j], a2[j]);
    }

    float v[16];
#pragma unroll
    for (int j = 0; j < 8; j++) {
        v[2 * j]     = lo2(a2[j]);
        v[2 * j + 1] = hi2(a2[j]);
    }

#pragma unroll
    for (int e = 0; e < 16; e++) v[e] += __shfl_xor_sync(0xffffffffu, v[e], 16);
    {
        bool h8 = lane & 8;
#pragma unroll
        for (int k = 0; k < 8; k++) {
            float mine = h8 ? v[k + 8] : v[k];
            float send = h8 ? v[k] : v[k + 8];
            v[k] = mine + __shfl_xor_sync(0xffffffffu, send, 8);
        }
        bool h4 = lane & 4;
#pragma unroll
        for (int k = 0; k < 4; k++) {
            float mine = h4 ? v[k + 4] : v[k];
            float send = h4 ? v[k] : v[k + 4];
            v[k] = mine + __shfl_xor_sync(0xffffffffu, send, 4);
        }
        bool h2 = lane & 2;
#pragma unroll
        for (int k = 0; k < 2; k++) {
            float mine = h2 ? v[k + 2] : v[k];
            float send = h2 ? v[k] : v[k + 2];
            v[k] = mine + __shfl_xor_sync(0xffffffffu, send, 2);
        }
        bool h1 = lane & 1;
        {
            float mine = h1 ? v[1] : v[0];
            float send = h1 ? v[0] : v[1];
            v[0] = mine + __shfl_xor_sync(0xffffffffu, send, 1);
        }
    }
#pragma unroll
    for (int o = 16; o; o >>= 1) {
        sum += __shfl_xor_sync(0xffffffffu, sum, o);
        sq  += __shfl_xor_sync(0xffffffffu, sq, o);
    }
    float mu = sum * (1.f / DIM);
    float rstd = rsqrtf(sq * (1.f / DIM) - mu * mu + 1e-5f);

    if (lane < 16) {
        float proj = rstd * (v[0] - mu * s_S[lane]) + s_c[lane];
        ((float*)&g_proj4[slot * 4])[lane] = -2.f * proj;
    }
    if (lane == 0) g_key[slot] = ~0ull;
}

// ===== Kernel 2: codes-in-registers argmin + lse + (last block) finalize =====
// Each lane owns 2 codes (e-pairs + sq) in REGISTERS; the token loop broadcasts
// one 64B proj row per iteration from smem. Argmin across lanes via mantissa-
// embedded index + shfl fmin; per-warp bests in smem; block-final atomicMin.
__global__ void __launch_bounds__(256, 3) k_dist(const float* __restrict__ emb,
                                                 float* __restrict__ out, int out_n) {
    int tid = threadIdx.x;
    int lane = tid & 31, wid = tid >> 5;
    int cnt = g_count;

    if (blockIdx.y == NSPLIT) {
        // ---- lse block (depends only on g_logits from k_front) ----
        if (blockIdx.x == 0) {
            __shared__ float redf[8];
            __shared__ float s_bc;
            float m = -3.4e38f;
#pragma unroll
            for (int i = tid; i < NCODE; i += 256) m = fmaxf(m, g_logits[i]);
#pragma unroll
            for (int o = 16; o; o >>= 1) m = fmaxf(m, __shfl_xor_sync(0xffffffffu, m, o));
            if (lane == 0) redf[wid] = m;
            __syncthreads();
            if (tid == 0) {
                float v = redf[0];
#pragma unroll
                for (int i = 1; i < 8; i++) v = fmaxf(v, redf[i]);
                s_bc = v;
            }
            __syncthreads();
            float M = s_bc;
            float s = 0.f;
#pragma unroll
            for (int i = tid; i < NCODE; i += 256) s += __expf(g_logits[i] - M);
#pragma unroll
            for (int o = 16; o; o >>= 1) s += __shfl_xor_sync(0xffffffffu, s, o);
            __syncthreads();
            if (lane == 0) redf[wid] = s;
            __syncthreads();
            if (tid == 0) {
                float v = 0.f;
#pragma unroll
                for (int i = 0; i < 8; i++) v += redf[i];
                g_lse = M + logf(v);
            }
        }
    } else if (blockIdx.x * TOKS_PER_DBLK < cnt) {
        __shared__ __align__(16) float s_p[TOKS_PER_DBLK * 16];     // proj rows, 8KB
        __shared__ float s_best[8 * TOKS_PER_DBLK];                 // per-warp bests, 4KB
        int nb = blockIdx.y * CODES_PER_BLK;
        int tbase = blockIdx.x * TOKS_PER_DBLK;

        // stage 128 proj rows (coalesced float4 copy)
        for (int i = tid; i < TOKS_PER_DBLK * 4; i += 256)
            ((float4*)s_p)[i] = ((const float4*)g_proj4)[tbase * 4 + i];

        // each lane loads its 2 codes into registers (e-pairs + (sq,0))
        int li0 = wid * 64 + lane;           // local code index 0..511
        int li1 = li0 + 32;
        int c0 = nb + li0, c1 = nb + li1;
        ull e0[8], e1[8], sq0, sq1;
        {
            float a[16], b[16];
            float sa = 0.f, sb = 0.f;
#pragma unroll
            for (int e = 0; e < 16; e++) {
                a[e] = __ldg(&emb[e * NCODE + c0]);
                b[e] = __ldg(&emb[e * NCODE + c1]);
                sa = fmaf(a[e], a[e], sa);
                sb = fmaf(b[e], b[e], sb);
            }
#pragma unroll
            for (int k = 0; k < 8; k++) {
                e0[k] = pk2(a[2 * k], a[2 * k + 1]);
                e1[k] = pk2(b[2 * k], b[2 * k + 1]);
            }
            sq0 = pk2(sa, 0.f);
            sq1 = pk2(sb, 0.f);
        }
        __syncthreads();

#pragma unroll 2
        for (int t = 0; t < TOKS_PER_DBLK; t++) {
            const ulonglong2* pr = (const ulonglong2*)(s_p + t * 16);
            ull a0 = sq0, a1 = sq1;
#pragma unroll
            for (int k = 0; k < 4; k++) {
                ulonglong2 q = pr[k];          // (p0,p1),(p2,p3) pairs of -2*proj
                a0 = ffma2((ull)q.x, e0[2 * k],     a0);
                a0 = ffma2((ull)q.y, e0[2 * k + 1], a0);
                a1 = ffma2((ull)q.x, e1[2 * k],     a1);
                a1 = ffma2((ull)q.y, e1[2 * k + 1], a1);
            }
            float d0 = lo2(a0) + hi2(a0);
            float d1 = lo2(a1) + hi2(a1);
            float v = fminf(embed_idx9(d0, (unsigned)li0),
                            embed_idx9(d1, (unsigned)li1));
#pragma unroll
            for (int o = 16; o; o >>= 1)
                v = fminf(v, __shfl_xor_sync(0xffffffffu, v, o));
            if (lane == 0) s_best[wid * TOKS_PER_DBLK + t] = v;
        }
        __syncthreads();

        if (tid < TOKS_PER_DBLK) {
            int slot = tbase + tid;
            if (slot < cnt) {
                float v = s_best[tid];
#pragma unroll
                for (int w = 1; w < 8; w++)
                    v = fminf(v, s_best[w * TOKS_PER_DBLK + tid]);
                unsigned ub = __float_as_uint(v);
                int bi = (int)(ub & 511u);
                unsigned mk = (ub & 0x80000000u) ? ~ub : (ub | 0x80000000u);
                atomicMin(&g_key[slot], (((ull)mk) << 32) | (unsigned)(nb + bi));
            }
        }
    }

    // ---- ticket: last block of the whole grid finalizes ----
    __shared__ int s_last;
    __syncthreads();
    if (tid == 0) {
        __threadfence();
        int total = gridDim.x * gridDim.y;
        int old = atomicAdd(&g_ticket, 1);
        s_last = (old == total - 1) ? 1 : 0;
    }
    __syncthreads();
    if (!s_last) return;
    __threadfence();

    __shared__ double redd[8];
    double acc = 0.0;
    for (int slot = tid; slot < cnt; slot += 256) {
        unsigned nidx = (unsigned)(g_key[slot] & 0xffffffffu);
        acc += (double)g_logits[nidx];
    }
#pragma unroll
    for (int o = 16; o; o >>= 1) acc += __shfl_xor_sync(0xffffffffu, acc, o);
    if (lane == 0) redd[wid] = acc;
    __syncthreads();
    if (tid == 0) {
        double t = 0.0;
#pragma unroll
        for (int i = 0; i < 8; i++) t += redd[i];
        float loss = (float)((double)g_lse - t / (double)cnt);   // C == 1
        for (int i = 0; i < out_n; i++) out[i] = loss;
        g_count = 0;    // reset for next graph replay
        g_ticket = 0;
    }
}

extern "C" void kernel_launch(void* const* d_in, const int* in_sizes, int n_in,
                              void* d_out, int out_size) {
    (void)in_sizes; (void)n_in;
    const float* xs    = (const float*)d_in[0];
    const void*  pad   = d_in[1];
    const void*  mm    = d_in[2];
    const float* gamma = (const float*)d_in[3];
    const float* beta  = (const float*)d_in[4];
    const float* P     = (const float*)d_in[5];
    const float* emb   = (const float*)d_in[6];   // (1,16,8192)
    const float* W     = (const float*)d_in[7];   // (1,256,8192)
    const float* me    = (const float*)d_in[8];

    k_front<<<LN_BLOCKS + LG_BLOCKS, 512>>>(xs, pad, mm, gamma, beta, P, W, me);
    dim3 gd(NTOK / TOKS_PER_DBLK, NSPLIT + 1);    // 64 x 17 (y==16 -> lse block)
    k_dist<<<gd, 256>>>(emb, (float*)d_out, out_size);
}

// round 14
// speedup vs baseline: 1.1556x; 1.1556x over previous
#include <cuda_runtime.h>
#include <cstdint>

#define NTOK 8192
#define DIM 256
#define EDIM 16
#define NCODE 8192
#define CHUNK 64                   // codes per dist block
#define NSPLIT (NCODE / CHUNK)     // 128
#define TOKS_PER_DBLK 512          // 256 threads x 2 tokens
#define LN_BLOCKS 512              // 16 tokens/block, warp-per-token
#define LG_BLOCKS 32               // 256 codes/block
#define EPITCH 20                  // floats per code row: 16 emb + (sq,0) + pad (80B)

typedef unsigned long long ull;

__device__ int g_count;                 // zero-init; reset by last dist block
__device__ int g_ticket;                // zero-init; reset by last dist block
__device__ float4 g_proj4[NTOK * 4];    // [slot][16] floats, PRE-SCALED by -2
__device__ float g_logits[NCODE];
__device__ float g_lse;
__device__ ull g_key[NTOK];

__device__ __forceinline__ ull pk2(float lo, float hi) {
    ull r;
    asm("mov.b64 %0, {%1, %2};" : "=l"(r) : "f"(lo), "f"(hi));
    return r;
}
__device__ __forceinline__ ull ffma2(ull a, ull b, ull c) {
    ull d;
    asm("fma.rn.f32x2 %0, %1, %2, %3;" : "=l"(d) : "l"(a), "l"(b), "l"(c));
    return d;
}
__device__ __forceinline__ float lo2(ull a) { return __uint_as_float((unsigned)a); }
__device__ __forceinline__ float hi2(ull a) { return __uint_as_float((unsigned)(a >> 32)); }

// embed 7-bit local index into low mantissa bits (order perturbation <= 2^-17 rel)
__device__ __forceinline__ float embed_idx(float d, unsigned idx) {
    return __uint_as_float((__float_as_uint(d) & 0xFFFFFF80u) | idx);
}

// ================= Kernel 1: block-specialized front =================
__global__ void __launch_bounds__(512) k_front(const float* __restrict__ xs,
                                               const void* __restrict__ pad,
                                               const void* __restrict__ mm,
                                               const float* __restrict__ gamma,
                                               const float* __restrict__ beta,
                                               const float* __restrict__ P,
                                               const float* __restrict__ W,
                                               const float* __restrict__ me) {
    int tid = threadIdx.x;
    int bx = blockIdx.x;

    if (bx >= LN_BLOCKS) {
        // ---- logits branch: 256 codes/block, 2 d-halves ----
        __shared__ float s_me[DIM];
        __shared__ float s_part[256];
        for (int i = tid; i < DIM; i += 512) s_me[i] = me[i];
        __syncthreads();
        int nl = tid & 255;
        int half = tid >> 8;
        int n = (bx - LN_BLOCKS) * 256 + nl;
        int d0 = half * 128;
        float a0 = 0.f, a1 = 0.f;
#pragma unroll 8
        for (int d = 0; d < 128; d += 2) {
            a0 = fmaf(s_me[d0 + d],     __ldg(&W[(size_t)(d0 + d)     * NCODE + n]), a0);
            a1 = fmaf(s_me[d0 + d + 1], __ldg(&W[(size_t)(d0 + d + 1) * NCODE + n]), a1);
        }
        float acc = a0 + a1;
        if (half == 1) s_part[nl] = acc;
        __syncthreads();
        if (half == 0) g_logits[n] = acc + s_part[nl];
        return;
    }

    // ---- LN + projection branch (warp per token, single pass) ----
    __shared__ __align__(16) ull s_P2[DIM * 9];   // gamma*P packed (e,e+1) f32x2, pitch 9 ull
    __shared__ float s_Pb[DIM * 17];              // beta*P, pitch 17
    __shared__ float s_redS[128], s_redC[128];
    __shared__ float s_S[16], s_c[16];
    __shared__ int   s_mm32[16], s_pd32[16];
    __shared__ unsigned s_mm8[4], s_pd8[4];
    __shared__ int   s_slot[16];

    int lane = tid & 31, wid = tid >> 5;

    int ni = 0, nf = 0;
    if (tid < 256) {
        int d = tid;
        float g = gamma[d], b = beta[d];
        float4 p0 = ((const float4*)P)[d * 4 + 0];
        float4 p1 = ((const float4*)P)[d * 4 + 1];
        float4 p2 = ((const float4*)P)[d * 4 + 2];
        float4 p3 = ((const float4*)P)[d * 4 + 3];
        ull* row = &s_P2[d * 9];
        row[0] = pk2(g * p0.x, g * p0.y); row[1] = pk2(g * p0.z, g * p0.w);
        row[2] = pk2(g * p1.x, g * p1.y); row[3] = pk2(g * p1.z, g * p1.w);
        row[4] = pk2(g * p2.x, g * p2.y); row[5] = pk2(g * p2.z, g * p2.w);
        row[6] = pk2(g * p3.x, g * p3.y); row[7] = pk2(g * p3.z, g * p3.w);
        float* rb = &s_Pb[d * 17];
        rb[0] = b * p0.x; rb[1] = b * p0.y; rb[2]  = b * p0.z; rb[3]  = b * p0.w;
        rb[4] = b * p1.x; rb[5] = b * p1.y; rb[6]  = b * p1.z; rb[7]  = b * p1.w;
        rb[8] = b * p2.x; rb[9] = b * p2.y; rb[10] = b * p2.z; rb[11] = b * p2.w;
        rb[12] = b * p3.x; rb[13] = b * p3.y; rb[14] = b * p3.z; rb[15] = b * p3.w;
    } else {
        int t = tid - 256;
        // mask dtype detection over first 2048 bytes of masked_masks (512 words)
        {
            unsigned v = ((const unsigned*)mm)[t + 256];
            if (v != 0u && v != 1u) ni = 1;
            if (v != 0u && v != 0x3f800000u) nf = 1;
        }
        // preload this block's mask words (both dtype interpretations)
        if (t < 16) s_mm32[t] = ((const int*)mm)[bx * 16 + t];
        else if (t < 32) s_pd32[t - 16] = ((const int*)pad)[bx * 16 + (t - 16)];
        else if (t < 36) s_mm8[t - 32] = ((const unsigned*)mm)[bx * 4 + (t - 32)];
        else if (t < 40) s_pd8[t - 36] = ((const unsigned*)pad)[bx * 4 + (t - 36)];
    }
    int bni = __syncthreads_or(ni);
    int bnf = __syncthreads_or(nf);
    int e4 = (!bni || !bnf) ? 1 : 0;

    // ---- phase 2: slots (warp 0) + S/c partial sums (tids 128..383) ----
    if (tid < 32) {
        bool m = false;
        if (tid < 16) {
            if (e4) m = (s_mm32[tid] != 0) && (s_pd32[tid] != 0);
            else {
                unsigned mb = (s_mm8[tid >> 2] >> ((tid & 3) * 8)) & 255u;
                unsigned pb = (s_pd8[tid >> 2] >> ((tid & 3) * 8)) & 255u;
                m = mb && pb;
            }
        }
        unsigned bal = __ballot_sync(0xffffffffu, m);
        int base = 0;
        if (tid == 0 && bal) base = atomicAdd(&g_count, __popc(bal));
        base = __shfl_sync(0xffffffffu, base, 0);
        if (tid < 16)
            s_slot[tid] = m ? (base + __popc(bal & ((1u << tid) - 1))) : -1;
    } else if (tid >= 128 && tid < 384) {
        int t = tid - 128;
        int e = t & 15, ch = (t >> 4) & 7;
        float s = 0.f;
        if (t < 128) {
            const float* pf = (const float*)s_P2;   // pitch 18 floats
#pragma unroll
            for (int i = 0; i < 32; i++) s += pf[(ch * 32 + i) * 18 + e];
            s_redS[ch * 16 + e] = s;
        } else {
#pragma unroll
            for (int i = 0; i < 32; i++) s += s_Pb[(ch * 32 + i) * 17 + e];
            s_redC[ch * 16 + e] = s;
        }
    }
    __syncthreads();
    if (tid < 16) {
        float v = 0.f;
#pragma unroll
        for (int c = 0; c < 8; c++) v += s_redS[c * 16 + tid];
        s_S[tid] = v;
    } else if (tid < 32) {
        int e = tid - 16;
        float v = 0.f;
#pragma unroll
        for (int c = 0; c < 8; c++) v += s_redC[c * 16 + e];
        s_c[e] = v;
    }
    __syncthreads();

    int slot = s_slot[wid];
    if (slot < 0) return;                 // whole warp exits (token unmasked)
    int tok = bx * 16 + wid;

    const float* xp = xs + (size_t)tok * DIM + lane;
    ull a2[8];
#pragma unroll
    for (int j = 0; j < 8; j++) a2[j] = 0ull;
    float sum = 0.f, sq = 0.f;
#pragma unroll
    for (int s = 0; s < 8; s++) {
        float xv = xp[32 * s];
        sum += xv; sq = fmaf(xv, xv, sq);
        ull x2 = pk2(xv, xv);
        const ull* pr = &s_P2[(lane + 32 * s) * 9];
#pragma unroll
        for (int j = 0; j < 8; j++) a2[j] = ffma2(x2, pr[j], a2[j]);
    }

    float v[16];
#pragma unroll
    for (int j = 0; j < 8; j++) {
        v[2 * j]     = lo2(a2[j]);
        v[2 * j + 1] = hi2(a2[j]);
    }

#pragma unroll
    for (int e = 0; e < 16; e++) v[e] += __shfl_xor_sync(0xffffffffu, v[e], 16);
    {
        bool h8 = lane & 8;
#pragma unroll
        for (int k = 0; k < 8; k++) {
            float mine = h8 ? v[k + 8] : v[k];
            float send = h8 ? v[k] : v[k + 8];
            v[k] = mine + __shfl_xor_sync(0xffffffffu, send, 8);
        }
        bool h4 = lane & 4;
#pragma unroll
        for (int k = 0; k < 4; k++) {
            float mine = h4 ? v[k + 4] : v[k];
            float send = h4 ? v[k] : v[k + 4];
            v[k] = mine + __shfl_xor_sync(0xffffffffu, send, 4);
        }
        bool h2 = lane & 2;
#pragma unroll
        for (int k = 0; k < 2; k++) {
            float mine = h2 ? v[k + 2] : v[k];
            float send = h2 ? v[k] : v[k + 2];
            v[k] = mine + __shfl_xor_sync(0xffffffffu, send, 2);
        }
        bool h1 = lane & 1;
        {
            float mine = h1 ? v[1] : v[0];
            float send = h1 ? v[0] : v[1];
            v[0] = mine + __shfl_xor_sync(0xffffffffu, send, 1);
        }
    }
#pragma unroll
    for (int o = 16; o; o >>= 1) {
        sum += __shfl_xor_sync(0xffffffffu, sum, o);
        sq  += __shfl_xor_sync(0xffffffffu, sq, o);
    }
    float mu = sum * (1.f / DIM);
    float rstd = rsqrtf(sq * (1.f / DIM) - mu * mu + 1e-5f);

    if (lane < 16) {
        float proj = rstd * (v[0] - mu * s_S[lane]) + s_c[lane];
        ((float*)&g_proj4[slot * 4])[lane] = -2.f * proj;
    }
    if (lane == 0) g_key[slot] = ~0ull;
}

// ===== Kernel 2: argmin (e-pair FFMA2, 2 tok x 2 codes, fminf-embedded idx) =====
__global__ void __launch_bounds__(256, 4) k_dist(const float* __restrict__ emb,
                                                 float* __restrict__ out, int out_n) {
    int tid = threadIdx.x;
    int cnt = g_count;

    if (blockIdx.y == NSPLIT) {
        // ---- lse block (depends only on g_logits from k_front) ----
        if (blockIdx.x == 0) {
            __shared__ float redf[8];
            __shared__ float s_bc;
            int lane = tid & 31, wid = tid >> 5;
            float m = -3.4e38f;
#pragma unroll
            for (int i = tid; i < NCODE; i += 256) m = fmaxf(m, g_logits[i]);
#pragma unroll
            for (int o = 16; o; o >>= 1) m = fmaxf(m, __shfl_xor_sync(0xffffffffu, m, o));
            if (lane == 0) redf[wid] = m;
            __syncthreads();
            if (tid == 0) {
                float v = redf[0];
#pragma unroll
                for (int i = 1; i < 8; i++) v = fmaxf(v, redf[i]);
                s_bc = v;
            }
            __syncthreads();
            float M = s_bc;
            float s = 0.f;
#pragma unroll
            for (int i = tid; i < NCODE; i += 256) s += __expf(g_logits[i] - M);
#pragma unroll
            for (int o = 16; o; o >>= 1) s += __shfl_xor_sync(0xffffffffu, s, o);
            __syncthreads();
            if (lane == 0) redf[wid] = s;
            __syncthreads();
            if (tid == 0) {
                float v = 0.f;
#pragma unroll
                for (int i = 0; i < 8; i++) v += redf[i];
                g_lse = M + logf(v);
            }
        }
    } else if (blockIdx.x * TOKS_PER_DBLK < cnt) {
        __shared__ __align__(16) float s_e[CHUNK * EPITCH];  // raw 16 floats + (sq,0) + pad
        int nb = blockIdx.y * CHUNK;
        int tbase = blockIdx.x * TOKS_PER_DBLK;

        if (tid < CHUNK) {
            int n = nb + tid;
            float v[16]; float sq = 0.f;
#pragma unroll
            for (int e = 0; e < 16; e++) { v[e] = __ldg(&emb[e * NCODE + n]); sq = fmaf(v[e], v[e], sq); }
            float4* r4 = (float4*)&s_e[tid * EPITCH];
            r4[0] = make_float4(v[0], v[1], v[2], v[3]);
            r4[1] = make_float4(v[4], v[5], v[6], v[7]);
            r4[2] = make_float4(v[8], v[9], v[10], v[11]);
            r4[3] = make_float4(v[12], v[13], v[14], v[15]);
            *(float2*)&s_e[tid * EPITCH + 16] = make_float2(sq, 0.f);
        }
        __syncthreads();

        int s0 = tbase + tid * 2;            // 2 tokens per thread
        ull pA[8], pB[8];
        {
            const float4* qa = (const float4*)&g_proj4[(s0 + 0) * 4];
            const float4* qb = (const float4*)&g_proj4[(s0 + 1) * 4];
#pragma unroll
            for (int j = 0; j < 4; j++) {
                float4 a = qa[j], b = qb[j];
                pA[2 * j] = pk2(a.x, a.y); pA[2 * j + 1] = pk2(a.z, a.w);
                pB[2 * j] = pk2(b.x, b.y); pB[2 * j + 1] = pk2(b.z, b.w);
            }
        }

        float bestA = 3.4e38f, bestB = 3.4e38f;

#pragma unroll 4
        for (int i = 0; i < CHUNK; i += 2) {
            const ulonglong2* r0 = (const ulonglong2*)(s_e + i * EPITCH);
            const ulonglong2* r1 = (const ulonglong2*)(s_e + (i + 1) * EPITCH);
            ull sqa = *(const ull*)(s_e + i * EPITCH + 16);       // (sq, 0)
            ull sqb = *(const ull*)(s_e + (i + 1) * EPITCH + 16);
            ull aA0 = sqa, aA1 = sqb, aB0 = sqa, aB1 = sqb;       // 4 indep chains
#pragma unroll
            for (int k = 0; k < 4; k++) {
                ulonglong2 q0 = r0[k];
                ulonglong2 q1 = r1[k];
                aA0 = ffma2(pA[2 * k],     (ull)q0.x, aA0);
                aA0 = ffma2(pA[2 * k + 1], (ull)q0.y, aA0);
                aB0 = ffma2(pB[2 * k],     (ull)q0.x, aB0);
                aB0 = ffma2(pB[2 * k + 1], (ull)q0.y, aB0);
                aA1 = ffma2(pA[2 * k],     (ull)q1.x, aA1);
                aA1 = ffma2(pA[2 * k + 1], (ull)q1.y, aA1);
                aB1 = ffma2(pB[2 * k],     (ull)q1.x, aB1);
                aB1 = ffma2(pB[2 * k + 1], (ull)q1.y, aB1);
            }
            float dA0 = lo2(aA0) + hi2(aA0);
            float dA1 = lo2(aA1) + hi2(aA1);
            float dB0 = lo2(aB0) + hi2(aB0);
            float dB1 = lo2(aB1) + hi2(aB1);
            bestA = fminf(bestA, embed_idx(dA0, (unsigned)i));
            bestA = fminf(bestA, embed_idx(dA1, (unsigned)(i + 1)));
            bestB = fminf(bestB, embed_idx(dB0, (unsigned)i));
            bestB = fminf(bestB, embed_idx(dB1, (unsigned)(i + 1)));
        }

        if (s0 < cnt) {
            unsigned ub = __float_as_uint(bestA);
            int bi = (int)(ub & 127u);
            unsigned mk = (ub & 0x80000000u) ? ~ub : (ub | 0x80000000u);
            atomicMin(&g_key[s0], (((ull)mk) << 32) | (unsigned)(nb + bi));
        }
        if (s0 + 1 < cnt) {
            unsigned ub = __float_as_uint(bestB);
            int bi = (int)(ub & 127u);
            unsigned mk = (ub & 0x80000000u) ? ~ub : (ub | 0x80000000u);
            atomicMin(&g_key[s0 + 1], (((ull)mk) << 32) | (unsigned)(nb + bi));
        }
    }

    // ---- ticket: last block of the whole grid finalizes ----
    __shared__ int s_last;
    __syncthreads();
    if (tid == 0) {
        __threadfence();
        int total = gridDim.x * gridDim.y;
        int old = atomicAdd(&g_ticket, 1);
        s_last = (old == total - 1) ? 1 : 0;
    }
    __syncthreads();
    if (!s_last) return;
    __threadfence();

    __shared__ double redd[8];
    int lane = tid & 31, wid = tid >> 5;
    double acc = 0.0;
    for (int slot = tid; slot < cnt; slot += 256) {
        unsigned nidx = (unsigned)(g_key[slot] & 0xffffffffu);
        acc += (double)g_logits[nidx];
    }
#pragma unroll
    for (int o = 16; o; o >>= 1) acc += __shfl_xor_sync(0xffffffffu, acc, o);
    if (lane == 0) redd[wid] = acc;
    __syncthreads();
    if (tid == 0) {
        double t = 0.0;
#pragma unroll
        for (int i = 0; i < 8; i++) t += redd[i];
        float loss = (float)((double)g_lse - t / (double)cnt);   // C == 1
        for (int i = 0; i < out_n; i++) out[i] = loss;
        g_count = 0;    // reset for next graph replay
        g_ticket = 0;
    }
}

extern "C" void kernel_launch(void* const* d_in, const int* in_sizes, int n_in,
                              void* d_out, int out_size) {
    (void)in_sizes; (void)n_in;
    const float* xs    = (const float*)d_in[0];
    const void*  pad   = d_in[1];
    const void*  mm    = d_in[2];
    const float* gamma = (const float*)d_in[3];
    const float* beta  = (const float*)d_in[4];
    const float* P     = (const float*)d_in[5];
    const float* emb   = (const float*)d_in[6];   // (1,16,8192)
    const float* W     = (const float*)d_in[7];   // (1,256,8192)
    const float* me    = (const float*)d_in[8];

    k_front<<<LN_BLOCKS + LG_BLOCKS, 512>>>(xs, pad, mm, gamma, beta, P, W, me);
    dim3 gd(NTOK / TOKS_PER_DBLK, NSPLIT + 1);    // 16 x 129 (y==128 -> lse block)
    k_dist<<<gd, 256>>>(emb, (float*)d_out, out_size);
}

// round 16
// speedup vs baseline: 1.9942x; 1.7257x over previous
#include <cuda_runtime.h>
#include <cuda_bf16.h>
#include <cstdint>

#define NTOK 8192
#define DIM 256
#define EDIM 16
#define NCODE 8192
#define LN_BLOCKS 512              // front: 16 tokens/block, warp-per-token
#define LG_BLOCKS 32               // front: 256 codes/block
#define TILE_M 128                 // tokens per dist block (8 warps x 16)
#define NCHUNK 512                 // codes per dist block
#define NSPLIT (NCODE / NCHUNK)    // 16
#define GRID_X (NTOK / TILE_M)     // 64
#define BPITCH 12                  // words per code row in s_B (conflict-free)

typedef unsigned long long ull;

__device__ int g_count;                 // zero-init; reset by last dist block
__device__ int g_ticket;                // zero-init; reset by last dist block
__device__ unsigned g_projh[NTOK * 8];  // [slot][8] bf16x2 pairs (-2p_2j, -2p_2j+1)
__device__ float g_logits[NCODE];
__device__ float g_lse;
__device__ ull g_key[NTOK];

__device__ __forceinline__ ull pk2(float lo, float hi) {
    ull r; asm("mov.b64 %0, {%1, %2};" : "=l"(r) : "f"(lo), "f"(hi)); return r;
}
__device__ __forceinline__ ull ffma2(ull a, ull b, ull c) {
    ull d; asm("fma.rn.f32x2 %0, %1, %2, %3;" : "=l"(d) : "l"(a), "l"(b), "l"(c)); return d;
}
__device__ __forceinline__ float lo2(ull a) { return __uint_as_float((unsigned)a); }
__device__ __forceinline__ float hi2(ull a) { return __uint_as_float((unsigned)(a >> 32)); }
__device__ __forceinline__ unsigned pkbf(float lo, float hi) {
    unsigned r; asm("cvt.rn.bf16x2.f32 %0, %1, %2;" : "=r"(r) : "f"(hi), "f"(lo)); return r;
}
// embed 9-bit local code index into low mantissa bits
__device__ __forceinline__ float embed9(float d, unsigned idx) {
    return __uint_as_float((__float_as_uint(d) & 0xFFFFFE00u) | idx);
}
__device__ __forceinline__ void mma_bf16(float& c0, float& c1, float& c2, float& c3,
                                         unsigned a0, unsigned a1, unsigned a2, unsigned a3,
                                         unsigned b0, unsigned b1) {
    asm volatile(
        "mma.sync.aligned.m16n8k16.row.col.f32.bf16.bf16.f32 "
        "{%0,%1,%2,%3}, {%4,%5,%6,%7}, {%8,%9}, {%0,%1,%2,%3};"
        : "+f"(c0), "+f"(c1), "+f"(c2), "+f"(c3)
        : "r"(a0), "r"(a1), "r"(a2), "r"(a3), "r"(b0), "r"(b1));
}

// ================= Kernel 1: block-specialized front =================
__global__ void __launch_bounds__(512) k_front(const float* __restrict__ xs,
                                               const void* __restrict__ pad,
                                               const void* __restrict__ mm,
                                               const float* __restrict__ gamma,
                                               const float* __restrict__ beta,
                                               const float* __restrict__ P,
                                               const float* __restrict__ W,
                                               const float* __restrict__ me) {
    int tid = threadIdx.x;
    int bx = blockIdx.x;

    if (bx >= LN_BLOCKS) {
        // ---- logits branch: 256 codes/block, 2 d-halves ----
        __shared__ float s_me[DIM];
        __shared__ float s_part[256];
        for (int i = tid; i < DIM; i += 512) s_me[i] = me[i];
        __syncthreads();
        int nl = tid & 255;
        int half = tid >> 8;
        int n = (bx - LN_BLOCKS) * 256 + nl;
        int d0 = half * 128;
        float a0 = 0.f, a1 = 0.f;
#pragma unroll 8
        for (int d = 0; d < 128; d += 2) {
            a0 = fmaf(s_me[d0 + d],     __ldg(&W[(size_t)(d0 + d)     * NCODE + n]), a0);
            a1 = fmaf(s_me[d0 + d + 1], __ldg(&W[(size_t)(d0 + d + 1) * NCODE + n]), a1);
        }
        float acc = a0 + a1;
        if (half == 1) s_part[nl] = acc;
        __syncthreads();
        if (half == 0) g_logits[n] = acc + s_part[nl];
        return;
    }

    // ---- LN + projection branch (warp per token, single pass) ----
    __shared__ __align__(16) ull s_P2[DIM * 9];   // gamma*P packed (e,e+1) f32x2, pitch 9 ull
    __shared__ float s_Pb[DIM * 17];              // beta*P, pitch 17
    __shared__ float s_redS[128], s_redC[128];
    __shared__ float s_S[16], s_c[16];
    __shared__ int   s_mm32[16], s_pd32[16];
    __shared__ unsigned s_mm8[4], s_pd8[4];
    __shared__ int   s_slot[16];

    int lane = tid & 31, wid = tid >> 5;

    int ni = 0, nf = 0;
    if (tid < 256) {
        int d = tid;
        float g = gamma[d], b = beta[d];
        float4 p0 = ((const float4*)P)[d * 4 + 0];
        float4 p1 = ((const float4*)P)[d * 4 + 1];
        float4 p2 = ((const float4*)P)[d * 4 + 2];
        float4 p3 = ((const float4*)P)[d * 4 + 3];
        ull* row = &s_P2[d * 9];
        row[0] = pk2(g * p0.x, g * p0.y); row[1] = pk2(g * p0.z, g * p0.w);
        row[2] = pk2(g * p1.x, g * p1.y); row[3] = pk2(g * p1.z, g * p1.w);
        row[4] = pk2(g * p2.x, g * p2.y); row[5] = pk2(g * p2.z, g * p2.w);
        row[6] = pk2(g * p3.x, g * p3.y); row[7] = pk2(g * p3.z, g * p3.w);
        float* rb = &s_Pb[d * 17];
        rb[0] = b * p0.x; rb[1] = b * p0.y; rb[2]  = b * p0.z; rb[3]  = b * p0.w;
        rb[4] = b * p1.x; rb[5] = b * p1.y; rb[6]  = b * p1.z; rb[7]  = b * p1.w;
        rb[8] = b * p2.x; rb[9] = b * p2.y; rb[10] = b * p2.z; rb[11] = b * p2.w;
        rb[12] = b * p3.x; rb[13] = b * p3.y; rb[14] = b * p3.z; rb[15] = b * p3.w;
    } else {
        int t = tid - 256;
        // mask dtype detection over first 2048 bytes of masked_masks (512 words)
        {
            unsigned v = ((const unsigned*)mm)[t + 256];
            if (v != 0u && v != 1u) ni = 1;
            if (v != 0u && v != 0x3f800000u) nf = 1;
        }
        // preload this block's mask words (both dtype interpretations)
        if (t < 16) s_mm32[t] = ((const int*)mm)[bx * 16 + t];
        else if (t < 32) s_pd32[t - 16] = ((const int*)pad)[bx * 16 + (t - 16)];
        else if (t < 36) s_mm8[t - 32] = ((const unsigned*)mm)[bx * 4 + (t - 32)];
        else if (t < 40) s_pd8[t - 36] = ((const unsigned*)pad)[bx * 4 + (t - 36)];
    }
    int bni = __syncthreads_or(ni);
    int bnf = __syncthreads_or(nf);
    int e4 = (!bni || !bnf) ? 1 : 0;

    // ---- phase 2: slots (warp 0) + S/c partial sums (tids 128..383) ----
    if (tid < 32) {
        bool m = false;
        if (tid < 16) {
            if (e4) m = (s_mm32[tid] != 0) && (s_pd32[tid] != 0);
            else {
                unsigned mb = (s_mm8[tid >> 2] >> ((tid & 3) * 8)) & 255u;
                unsigned pb = (s_pd8[tid >> 2] >> ((tid & 3) * 8)) & 255u;
                m = mb && pb;
            }
        }
        unsigned bal = __ballot_sync(0xffffffffu, m);
        int base = 0;
        if (tid == 0 && bal) base = atomicAdd(&g_count, __popc(bal));
        base = __shfl_sync(0xffffffffu, base, 0);
        if (tid < 16)
            s_slot[tid] = m ? (base + __popc(bal & ((1u << tid) - 1))) : -1;
    } else if (tid >= 128 && tid < 384) {
        int t = tid - 128;
        int e = t & 15, ch = (t >> 4) & 7;
        float s = 0.f;
        if (t < 128) {
            const float* pf = (const float*)s_P2;   // pitch 18 floats
#pragma unroll
            for (int i = 0; i < 32; i++) s += pf[(ch * 32 + i) * 18 + e];
            s_redS[ch * 16 + e] = s;
        } else {
#pragma unroll
            for (int i = 0; i < 32; i++) s += s_Pb[(ch * 32 + i) * 17 + e];
            s_redC[ch * 16 + e] = s;
        }
    }
    __syncthreads();
    if (tid < 16) {
        float v = 0.f;
#pragma unroll
        for (int c = 0; c < 8; c++) v += s_redS[c * 16 + tid];
        s_S[tid] = v;
    } else if (tid < 32) {
        int e = tid - 16;
        float v = 0.f;
#pragma unroll
        for (int c = 0; c < 8; c++) v += s_redC[c * 16 + e];
        s_c[e] = v;
    }
    __syncthreads();

    int slot = s_slot[wid];
    if (slot < 0) return;                 // whole warp exits (token unmasked)
    int tok = bx * 16 + wid;

    const float* xp = xs + (size_t)tok * DIM + lane;
    ull a2[8];
#pragma unroll
    for (int j = 0; j < 8; j++) a2[j] = 0ull;
    float sum = 0.f, sq = 0.f;
#pragma unroll
    for (int s = 0; s < 8; s++) {
        float xv = xp[32 * s];
        sum += xv; sq = fmaf(xv, xv, sq);
        ull x2 = pk2(xv, xv);
        const ull* pr = &s_P2[(lane + 32 * s) * 9];
#pragma unroll
        for (int j = 0; j < 8; j++) a2[j] = ffma2(x2, pr[j], a2[j]);
    }

    float v[16];
#pragma unroll
    for (int j = 0; j < 8; j++) { v[2 * j] = lo2(a2[j]); v[2 * j + 1] = hi2(a2[j]); }

#pragma unroll
    for (int e = 0; e < 16; e++) v[e] += __shfl_xor_sync(0xffffffffu, v[e], 16);
    {
        bool h8 = lane & 8;
#pragma unroll
        for (int k = 0; k < 8; k++) {
            float mine = h8 ? v[k + 8] : v[k];
            float send = h8 ? v[k] : v[k + 8];
            v[k] = mine + __shfl_xor_sync(0xffffffffu, send, 8);
        }
        bool h4 = lane & 4;
#pragma unroll
        for (int k = 0; k < 4; k++) {
            float mine = h4 ? v[k + 4] : v[k];
            float send = h4 ? v[k] : v[k + 4];
            v[k] = mine + __shfl_xor_sync(0xffffffffu, send, 4);
        }
        bool h2 = lane & 2;
#pragma unroll
        for (int k = 0; k < 2; k++) {
            float mine = h2 ? v[k + 2] : v[k];
            float send = h2 ? v[k] : v[k + 2];
            v[k] = mine + __shfl_xor_sync(0xffffffffu, send, 2);
        }
        bool h1 = lane & 1;
        {
            float mine = h1 ? v[1] : v[0];
            float send = h1 ? v[0] : v[1];
            v[0] = mine + __shfl_xor_sync(0xffffffffu, send, 1);
        }
    }
#pragma unroll
    for (int o = 16; o; o >>= 1) {
        sum += __shfl_xor_sync(0xffffffffu, sum, o);
        sq  += __shfl_xor_sync(0xffffffffu, sq, o);
    }
    float mu = sum * (1.f / DIM);
    float rstd = rsqrtf(sq * (1.f / DIM) - mu * mu + 1e-5f);

    // pack -2*proj as bf16x2 pairs (word j = (p_2j, p_2j+1))
    float projv = rstd * (v[0] - mu * s_S[lane & 15]) + s_c[lane & 15];
    float m2 = -2.f * projv;
    float m2hi = __shfl_down_sync(0xffffffffu, m2, 1);
    if (lane < 16 && (lane & 1) == 0)
        g_projh[slot * 8 + (lane >> 1)] = pkbf(m2, m2hi);
    if (lane == 0) g_key[slot] = ~0ull;
}

// ===== Kernel 2: HMMA (mma.sync bf16) distance + argmin + lse + finalize =====
__global__ void __launch_bounds__(256) k_dist(const float* __restrict__ emb,
                                              float* __restrict__ out, int out_n) {
    int tid = threadIdx.x;
    int lane = tid & 31, wid = tid >> 5;
    int cnt = g_count;

    if (blockIdx.y == NSPLIT) {
        // ---- lse block ----
        if (blockIdx.x == 0) {
            __shared__ float redf[8];
            __shared__ float s_bc;
            float m = -3.4e38f;
#pragma unroll
            for (int i = tid; i < NCODE; i += 256) m = fmaxf(m, g_logits[i]);
#pragma unroll
            for (int o = 16; o; o >>= 1) m = fmaxf(m, __shfl_xor_sync(0xffffffffu, m, o));
            if (lane == 0) redf[wid] = m;
            __syncthreads();
            if (tid == 0) {
                float v = redf[0];
#pragma unroll
                for (int i = 1; i < 8; i++) v = fmaxf(v, redf[i]);
                s_bc = v;
            }
            __syncthreads();
            float M = s_bc;
            float s = 0.f;
#pragma unroll
            for (int i = tid; i < NCODE; i += 256) s += __expf(g_logits[i] - M);
#pragma unroll
            for (int o = 16; o; o >>= 1) s += __shfl_xor_sync(0xffffffffu, s, o);
            __syncthreads();
            if (lane == 0) redf[wid] = s;
            __syncthreads();
            if (tid == 0) {
                float v = 0.f;
#pragma unroll
                for (int i = 0; i < 8; i++) v += redf[i];
                g_lse = M + logf(v);
            }
        }
    } else if ((int)blockIdx.x * TILE_M < cnt) {
        __shared__ __align__(16) unsigned s_B[NCHUNK * BPITCH];  // bf16x2 e-pairs, pitch 12
        __shared__ __align__(8) float s_sq[NCHUNK];
        int nb = blockIdx.y * NCHUNK;
        int tbase = blockIdx.x * TILE_M;

        // stage 512 codes: 8 bf16x2 e-pair words + sq each
        for (int c = tid; c < NCHUNK; c += 256) {
            int n = nb + c;
            float sq = 0.f;
            unsigned w[8];
#pragma unroll
            for (int k = 0; k < 8; k++) {
                float e0 = __ldg(&emb[(2 * k) * NCODE + n]);
                float e1 = __ldg(&emb[(2 * k + 1) * NCODE + n]);
                sq = fmaf(e0, e0, fmaf(e1, e1, sq));
                w[k] = pkbf(e0, e1);
            }
            unsigned* row = &s_B[c * BPITCH];
#pragma unroll
            for (int k = 0; k < 8; k++) row[k] = w[k];
            s_sq[c] = sq;
        }

        // A fragment: warp owns 16 tokens (rows); qr = lane/4, qc = lane%4
        int qr = lane >> 2, qc = lane & 3;
        int w16 = tbase + wid * 16;
        unsigned A0 = g_projh[(w16 + qr) * 8 + qc];
        unsigned A1 = g_projh[(w16 + qr + 8) * 8 + qc];
        unsigned A2 = g_projh[(w16 + qr) * 8 + qc + 4];
        unsigned A3 = g_projh[(w16 + qr + 8) * 8 + qc + 4];
        __syncthreads();

        float bL = 3.4e38f, bH = 3.4e38f;
#pragma unroll 4
        for (int t = 0; t < NCHUNK / 8; t++) {
            int n0 = t * 8;
            unsigned b0 = s_B[(n0 + qr) * BPITCH + qc];
            unsigned b1 = s_B[(n0 + qr) * BPITCH + qc + 4];
            float2 sq2 = *(const float2*)&s_sq[n0 + 2 * qc];
            float c0 = sq2.x, c1 = sq2.y, c2 = sq2.x, c3 = sq2.y;
            mma_bf16(c0, c1, c2, c3, A0, A1, A2, A3, b0, b1);
            unsigned i0 = (unsigned)(n0 + 2 * qc);
            bL = fminf(bL, embed9(c0, i0));
            bL = fminf(bL, embed9(c1, i0 + 1));
            bH = fminf(bH, embed9(c2, i0));
            bH = fminf(bH, embed9(c3, i0 + 1));
        }
        // reduce across the quad (qc axis)
        bL = fminf(bL, __shfl_xor_sync(0xffffffffu, bL, 1));
        bL = fminf(bL, __shfl_xor_sync(0xffffffffu, bL, 2));
        bH = fminf(bH, __shfl_xor_sync(0xffffffffu, bH, 1));
        bH = fminf(bH, __shfl_xor_sync(0xffffffffu, bH, 2));

        if (qc == 0) {
            int tokL = w16 + qr, tokH = w16 + qr + 8;
            if (tokL < cnt) {
                unsigned ub = __float_as_uint(bL);
                int bi = (int)(ub & 511u);
                unsigned mk = (ub & 0x80000000u) ? ~ub : (ub | 0x80000000u);
                atomicMin(&g_key[tokL], (((ull)mk) << 32) | (unsigned)(nb + bi));
            }
            if (tokH < cnt) {
                unsigned ub = __float_as_uint(bH);
                int bi = (int)(ub & 511u);
                unsigned mk = (ub & 0x80000000u) ? ~ub : (ub | 0x80000000u);
                atomicMin(&g_key[tokH], (((ull)mk) << 32) | (unsigned)(nb + bi));
            }
        }
    }

    // ---- ticket: last block of the whole grid finalizes ----
    __shared__ int s_last;
    __syncthreads();
    if (tid == 0) {
        __threadfence();
        int total = gridDim.x * gridDim.y;
        int old = atomicAdd(&g_ticket, 1);
        s_last = (old == total - 1) ? 1 : 0;
    }
    __syncthreads();
    if (!s_last) return;
    __threadfence();

    __shared__ double redd[8];
    double acc = 0.0;
    for (int slot = tid; slot < cnt; slot += 256) {
        unsigned nidx = (unsigned)(g_key[slot] & 0xffffffffu);
        acc += (double)g_logits[nidx];
    }
#pragma unroll
    for (int o = 16; o; o >>= 1) acc += __shfl_xor_sync(0xffffffffu, acc, o);
    if (lane == 0) redd[wid] = acc;
    __syncthreads();
    if (tid == 0) {
        double t = 0.0;
#pragma unroll
        for (int i = 0; i < 8; i++) t += redd[i];
        float loss = (float)((double)g_lse - t / (double)cnt);   // C == 1
        for (int i = 0; i < out_n; i++) out[i] = loss;
        g_count = 0;    // reset for next graph replay
        g_ticket = 0;
    }
}

extern "C" void kernel_launch(void* const* d_in, const int* in_sizes, int n_in,
                              void* d_out, int out_size) {
    (void)in_sizes; (void)n_in;
    const float* xs    = (const float*)d_in[0];
    const void*  pad   = d_in[1];
    const void*  mm    = d_in[2];
    const float* gamma = (const float*)d_in[3];
    const float* beta  = (const float*)d_in[4];
    const float* P     = (const float*)d_in[5];
    const float* emb   = (const float*)d_in[6];   // (1,16,8192)
    const float* W     = (const float*)d_in[7];   // (1,256,8192)
    const float* me    = (const float*)d_in[8];

    k_front<<<LN_BLOCKS + LG_BLOCKS, 512>>>(xs, pad, mm, gamma, beta, P, W, me);
    dim3 gd(GRID_X, NSPLIT + 1);                  // 64 x 17 (y==16 -> lse block)
    k_dist<<<gd, 256>>>(emb, (float*)d_out, out_size);
}